// round 2
// baseline (speedup 1.0000x reference)
#include <cuda_runtime.h>
#include <stdint.h>

#define D 128
#define MAX_NODES 50000
#define BM 128

// Scratch: support = x @ W   (device global, no allocation allowed)
__device__ float g_support[(size_t)MAX_NODES * D];
__device__ int g_idx64;   // 1 if edge index arrays are int64, 0 if int32

// ---------------------------------------------------------------------------
// Detect index width. int64 values are all < 50000 < 2^32. If the buffer is
// actually int32, a u64 read packs two consecutive int32s and the high half
// is ~never zero across 16 samples.
// ---------------------------------------------------------------------------
__global__ void detect_idx_kernel(const void* idx) {
    const unsigned long long* p = (const unsigned long long*)idx;
    int is64 = 1;
    #pragma unroll
    for (int i = 0; i < 16; i++) {
        if (p[i] >= (1ULL << 32)) { is64 = 0; }
    }
    g_idx64 = is64;
}

// ---------------------------------------------------------------------------
// SGEMM: support[M,128] = x[M,128] @ W[128,128]
// One block = 128 rows. Full W (64KB) + transposed A tile (128x132, 67.5KB)
// in dynamic smem. 256 threads, each computes an 8x8 micro-tile.
// ---------------------------------------------------------------------------
__global__ void __launch_bounds__(256, 1)
gemm_kernel(const float* __restrict__ x, const float* __restrict__ w, int M) {
    extern __shared__ float sm[];
    float* Wsh = sm;                 // [128][128] row-major (k-major, c contiguous)
    float* Ash = sm + D * D;         // [128][132] : Ash[k*132 + r_local]
    const int AS = 132;

    const int tid  = threadIdx.x;
    const int row0 = blockIdx.x * BM;

    // Load W (128x128 fp32) as float4, coalesced
    #pragma unroll
    for (int i = tid; i < (D * D) / 4; i += 256) {
        ((float4*)Wsh)[i] = ((const float4*)w)[i];
    }

    // Load A tile transposed: 128 rows x 128 cols, 16 float4 per thread
    #pragma unroll
    for (int l = 0; l < 16; l++) {
        int f = tid + 256 * l;        // float4 index within tile [0, 4096)
        int r = f >> 5;               // 32 float4 per row
        int q = f & 31;
        int k = q * 4;
        float4 v = make_float4(0.f, 0.f, 0.f, 0.f);
        int gr = row0 + r;
        if (gr < M) v = ((const float4*)(x + (size_t)gr * D))[q];
        Ash[(k + 0) * AS + r] = v.x;
        Ash[(k + 1) * AS + r] = v.y;
        Ash[(k + 2) * AS + r] = v.z;
        Ash[(k + 3) * AS + r] = v.w;
    }
    __syncthreads();

    const int tx = tid & 15;          // 16 col groups of 8
    const int ty = tid >> 4;          // 16 row groups of 8
    const int rbase = ty * 8;
    const int cbase = tx * 8;

    float acc[8][8];
    #pragma unroll
    for (int i = 0; i < 8; i++)
        #pragma unroll
        for (int j = 0; j < 8; j++) acc[i][j] = 0.f;

    #pragma unroll 8
    for (int k = 0; k < D; k++) {
        float4 a0 = *(const float4*)&Ash[k * AS + rbase];
        float4 a1 = *(const float4*)&Ash[k * AS + rbase + 4];
        float4 b0 = *(const float4*)&Wsh[k * D + cbase];
        float4 b1 = *(const float4*)&Wsh[k * D + cbase + 4];
        float a[8] = {a0.x, a0.y, a0.z, a0.w, a1.x, a1.y, a1.z, a1.w};
        float b[8] = {b0.x, b0.y, b0.z, b0.w, b1.x, b1.y, b1.z, b1.w};
        #pragma unroll
        for (int i = 0; i < 8; i++)
            #pragma unroll
            for (int j = 0; j < 8; j++)
                acc[i][j] = fmaf(a[i], b[j], acc[i][j]);
    }

    // Store 8x8 micro-tile
    #pragma unroll
    for (int i = 0; i < 8; i++) {
        int gr = row0 + rbase + i;
        if (gr < M) {
            float4* o = (float4*)(g_support + (size_t)gr * D + cbase);
            o[0] = make_float4(acc[i][0], acc[i][1], acc[i][2], acc[i][3]);
            o[1] = make_float4(acc[i][4], acc[i][5], acc[i][6], acc[i][7]);
        }
    }
}

// ---------------------------------------------------------------------------
// out[n][c] = bias[c]   (atomics then add on top)
// ---------------------------------------------------------------------------
__global__ void init_out_kernel(float* __restrict__ out,
                                const float* __restrict__ bias, int total4) {
    int i = blockIdx.x * blockDim.x + threadIdx.x;
    if (i < total4) {
        ((float4*)out)[i] = ((const float4*)bias)[i & 31];
    }
}

// ---------------------------------------------------------------------------
// Scatter: warp per edge. Lane l handles columns 4l..4l+3.
// out[row] += ew[e] * support[col]
// ---------------------------------------------------------------------------
__global__ void __launch_bounds__(256)
scatter_kernel(const float* __restrict__ ew,
               const void* __restrict__ er, const void* __restrict__ ec,
               float* __restrict__ out, int E) {
    int warp = (blockIdx.x * blockDim.x + threadIdx.x) >> 5;
    int lane = threadIdx.x & 31;
    if (warp >= E) return;

    long long row, col;
    if (g_idx64) {
        row = ((const long long*)er)[warp];
        col = ((const long long*)ec)[warp];
    } else {
        row = ((const int*)er)[warp];
        col = ((const int*)ec)[warp];
    }
    float w = __ldg(ew + warp);

    float4 s = *(const float4*)(g_support + (size_t)col * D + lane * 4);
    float* o = out + (size_t)row * D + lane * 4;
    atomicAdd(o + 0, s.x * w);
    atomicAdd(o + 1, s.y * w);
    atomicAdd(o + 2, s.z * w);
    atomicAdd(o + 3, s.w * w);
}

// ---------------------------------------------------------------------------
extern "C" void kernel_launch(void* const* d_in, const int* in_sizes, int n_in,
                              void* d_out, int out_size) {
    const float* x    = (const float*)d_in[0];
    const float* w    = (const float*)d_in[1];
    const float* bias = (const float*)d_in[2];
    const float* ew   = (const float*)d_in[3];
    const void*  er   = d_in[4];
    const void*  ec   = d_in[5];
    float* out = (float*)d_out;

    int M = in_sizes[0] / D;           // 50000
    int E = in_sizes[3];               // 800000

    const int gemm_smem = (D * D + D * 132) * (int)sizeof(float);  // 133120 B
    cudaFuncSetAttribute(gemm_kernel,
                         cudaFuncAttributeMaxDynamicSharedMemorySize, gemm_smem);

    detect_idx_kernel<<<1, 1>>>(er);

    gemm_kernel<<<(M + BM - 1) / BM, 256, gemm_smem>>>(x, w, M);

    int total4 = M * (D / 4);
    init_out_kernel<<<(total4 + 255) / 256, 256>>>(out, bias, total4);

    // one warp per edge, 8 warps per block
    int blocks = (E + 7) / 8;
    scatter_kernel<<<blocks, 256>>>(ew, er, ec, out, E);
}

// round 3
// speedup vs baseline: 2.4384x; 2.4384x over previous
#include <cuda_runtime.h>
#include <stdint.h>

#define D 128
#define MAX_NODES 50000
#define MAX_EDGES 800000
#define BM 128
#define SCAN_T 256

// ---- device scratch (no allocations allowed) ----
__device__ float g_support[(size_t)MAX_NODES * D];   // x @ W
__device__ int   g_cursor[MAX_NODES];                // counts -> start offsets -> end offsets
__device__ int   g_bsum[(MAX_NODES + SCAN_T - 1) / SCAN_T];
__device__ int   g_boff[(MAX_NODES + SCAN_T - 1) / SCAN_T];
__device__ int   g_scol[MAX_EDGES];                  // sorted-by-row col indices
__device__ float g_sw[MAX_EDGES];                    // sorted-by-row edge weights
__device__ int   g_idx64;

// ---------------------------------------------------------------------------
// Detect whether edge index buffers are int64 or int32.
// ---------------------------------------------------------------------------
__global__ void detect_idx_kernel(const void* idx) {
    const unsigned long long* p = (const unsigned long long*)idx;
    int is64 = 1;
    #pragma unroll
    for (int i = 0; i < 16; i++)
        if (p[i] >= (1ULL << 32)) is64 = 0;
    g_idx64 = is64;
}

__device__ __forceinline__ int load_idx(const void* buf, int e) {
    return g_idx64 ? (int)((const long long*)buf)[e] : ((const int*)buf)[e];
}

// ---------------------------------------------------------------------------
// SGEMM: support[M,128] = x[M,128] @ W[128,128]  (fp32, smem-blocked 8x8)
// ---------------------------------------------------------------------------
__global__ void __launch_bounds__(256, 1)
gemm_kernel(const float* __restrict__ x, const float* __restrict__ w, int M) {
    extern __shared__ float sm[];
    float* Wsh = sm;                 // [128][128]
    float* Ash = sm + D * D;         // [128][132] transposed
    const int AS = 132;

    const int tid  = threadIdx.x;
    const int row0 = blockIdx.x * BM;

    #pragma unroll
    for (int i = tid; i < (D * D) / 4; i += 256)
        ((float4*)Wsh)[i] = ((const float4*)w)[i];

    #pragma unroll
    for (int l = 0; l < 16; l++) {
        int f = tid + 256 * l;
        int r = f >> 5;
        int q = f & 31;
        int k = q * 4;
        float4 v = make_float4(0.f, 0.f, 0.f, 0.f);
        int gr = row0 + r;
        if (gr < M) v = ((const float4*)(x + (size_t)gr * D))[q];
        Ash[(k + 0) * AS + r] = v.x;
        Ash[(k + 1) * AS + r] = v.y;
        Ash[(k + 2) * AS + r] = v.z;
        Ash[(k + 3) * AS + r] = v.w;
    }
    __syncthreads();

    const int tx = tid & 15, ty = tid >> 4;
    const int rbase = ty * 8, cbase = tx * 8;

    float acc[8][8];
    #pragma unroll
    for (int i = 0; i < 8; i++)
        #pragma unroll
        for (int j = 0; j < 8; j++) acc[i][j] = 0.f;

    #pragma unroll 8
    for (int k = 0; k < D; k++) {
        float4 a0 = *(const float4*)&Ash[k * AS + rbase];
        float4 a1 = *(const float4*)&Ash[k * AS + rbase + 4];
        float4 b0 = *(const float4*)&Wsh[k * D + cbase];
        float4 b1 = *(const float4*)&Wsh[k * D + cbase + 4];
        float a[8] = {a0.x, a0.y, a0.z, a0.w, a1.x, a1.y, a1.z, a1.w};
        float b[8] = {b0.x, b0.y, b0.z, b0.w, b1.x, b1.y, b1.z, b1.w};
        #pragma unroll
        for (int i = 0; i < 8; i++)
            #pragma unroll
            for (int j = 0; j < 8; j++)
                acc[i][j] = fmaf(a[i], b[j], acc[i][j]);
    }

    #pragma unroll
    for (int i = 0; i < 8; i++) {
        int gr = row0 + rbase + i;
        if (gr < M) {
            float4* o = (float4*)(g_support + (size_t)gr * D + cbase);
            o[0] = make_float4(acc[i][0], acc[i][1], acc[i][2], acc[i][3]);
            o[1] = make_float4(acc[i][4], acc[i][5], acc[i][6], acc[i][7]);
        }
    }
}

// ---------------------------------------------------------------------------
// Counting-sort pipeline
// ---------------------------------------------------------------------------
__global__ void zero_count_kernel(int M) {
    int i = blockIdx.x * blockDim.x + threadIdx.x;
    if (i < M) g_cursor[i] = 0;
}

__global__ void hist_kernel(const void* __restrict__ er, int E) {
    int e = blockIdx.x * blockDim.x + threadIdx.x;
    if (e < E) atomicAdd(&g_cursor[load_idx(er, e)], 1);
}

// scan1: per-tile sums
__global__ void scan1_kernel(int M) {
    __shared__ int s[SCAN_T];
    int t = threadIdx.x;
    int i = blockIdx.x * SCAN_T + t;
    s[t] = (i < M) ? g_cursor[i] : 0;
    __syncthreads();
    #pragma unroll
    for (int off = SCAN_T / 2; off > 0; off >>= 1) {
        if (t < off) s[t] += s[t + off];
        __syncthreads();
    }
    if (t == 0) g_bsum[blockIdx.x] = s[0];
}

// scan2: single-block exclusive scan of tile sums (NB <= 256)
__global__ void scan2_kernel(int NB) {
    __shared__ int s[SCAN_T];
    int t = threadIdx.x;
    int v0 = (t < NB) ? g_bsum[t] : 0;
    s[t] = v0;
    __syncthreads();
    #pragma unroll
    for (int off = 1; off < SCAN_T; off <<= 1) {
        int v = (t >= off) ? s[t - off] : 0;
        __syncthreads();
        s[t] += v;
        __syncthreads();
    }
    if (t < NB) g_boff[t] = s[t] - v0;   // exclusive
}

// scan3: per-tile exclusive scan + tile offset -> start offsets in g_cursor
__global__ void scan3_kernel(int M) {
    __shared__ int s[SCAN_T];
    int t = threadIdx.x;
    int i = blockIdx.x * SCAN_T + t;
    int v0 = (i < M) ? g_cursor[i] : 0;
    s[t] = v0;
    __syncthreads();
    #pragma unroll
    for (int off = 1; off < SCAN_T; off <<= 1) {
        int v = (t >= off) ? s[t - off] : 0;
        __syncthreads();
        s[t] += v;
        __syncthreads();
    }
    if (i < M) g_cursor[i] = g_boff[blockIdx.x] + s[t] - v0;  // exclusive start
}

// reorder: place each edge at its row-grouped slot.
// After this kernel g_cursor[n] == end offset of row n.
__global__ void reorder_kernel(const float* __restrict__ ew,
                               const void* __restrict__ er,
                               const void* __restrict__ ec, int E) {
    int e = blockIdx.x * blockDim.x + threadIdx.x;
    if (e >= E) return;
    int row = load_idx(er, e);
    int col = load_idx(ec, e);
    int pos = atomicAdd(&g_cursor[row], 1);
    g_scol[pos] = col;
    g_sw[pos]   = ew[e];
}

// ---------------------------------------------------------------------------
// Segmented accumulate: one warp per node. Lane l owns cols [4l, 4l+4).
// out[n] = bias + sum_e w_e * support[col_e]   — no atomics.
// ---------------------------------------------------------------------------
__global__ void __launch_bounds__(256)
segment_kernel(const float* __restrict__ bias, float* __restrict__ out, int M) {
    int n = (blockIdx.x * blockDim.x + threadIdx.x) >> 5;
    int lane = threadIdx.x & 31;
    if (n >= M) return;

    int start = (n == 0) ? 0 : g_cursor[n - 1];
    int end   = g_cursor[n];

    float4 acc = ((const float4*)bias)[lane];

    int e = start;
    // 2-way unroll for MLP
    for (; e + 2 <= end; e += 2) {
        int   c0 = g_scol[e],     c1 = g_scol[e + 1];
        float w0 = g_sw[e],       w1 = g_sw[e + 1];
        float4 s0 = *(const float4*)(g_support + (size_t)c0 * D + lane * 4);
        float4 s1 = *(const float4*)(g_support + (size_t)c1 * D + lane * 4);
        acc.x = fmaf(w0, s0.x, acc.x); acc.y = fmaf(w0, s0.y, acc.y);
        acc.z = fmaf(w0, s0.z, acc.z); acc.w = fmaf(w0, s0.w, acc.w);
        acc.x = fmaf(w1, s1.x, acc.x); acc.y = fmaf(w1, s1.y, acc.y);
        acc.z = fmaf(w1, s1.z, acc.z); acc.w = fmaf(w1, s1.w, acc.w);
    }
    if (e < end) {
        int   c0 = g_scol[e];
        float w0 = g_sw[e];
        float4 s0 = *(const float4*)(g_support + (size_t)c0 * D + lane * 4);
        acc.x = fmaf(w0, s0.x, acc.x); acc.y = fmaf(w0, s0.y, acc.y);
        acc.z = fmaf(w0, s0.z, acc.z); acc.w = fmaf(w0, s0.w, acc.w);
    }

    ((float4*)(out + (size_t)n * D))[lane] = acc;
}

// ---------------------------------------------------------------------------
extern "C" void kernel_launch(void* const* d_in, const int* in_sizes, int n_in,
                              void* d_out, int out_size) {
    const float* x    = (const float*)d_in[0];
    const float* w    = (const float*)d_in[1];
    const float* bias = (const float*)d_in[2];
    const float* ew   = (const float*)d_in[3];
    const void*  er   = d_in[4];
    const void*  ec   = d_in[5];
    float* out = (float*)d_out;

    int M = in_sizes[0] / D;           // 50000
    int E = in_sizes[3];               // 800000
    int NB = (M + SCAN_T - 1) / SCAN_T;

    const int gemm_smem = (D * D + D * 132) * (int)sizeof(float);
    cudaFuncSetAttribute(gemm_kernel,
                         cudaFuncAttributeMaxDynamicSharedMemorySize, gemm_smem);

    detect_idx_kernel<<<1, 1>>>(er);

    gemm_kernel<<<(M + BM - 1) / BM, 256, gemm_smem>>>(x, w, M);

    zero_count_kernel<<<(M + 255) / 256, 256>>>(M);
    hist_kernel<<<(E + 255) / 256, 256>>>(er, E);
    scan1_kernel<<<NB, SCAN_T>>>(M);
    scan2_kernel<<<1, SCAN_T>>>(NB);
    scan3_kernel<<<NB, SCAN_T>>>(M);
    reorder_kernel<<<(E + 255) / 256, 256>>>(ew, er, ec, E);

    segment_kernel<<<(M + 7) / 8, 256>>>(bias, out, M);
}